// round 13
// baseline (speedup 1.0000x reference)
#include <cuda_runtime.h>
#include <cuda_fp16.h>
#include <math.h>
#include <stdint.h>

#define DIM     1024
#define HIDDEN  2560
#define NEXP    4
#define NTOK    8192
#define CAP     8192

#define TM  128
#define BK  32
#define PAD 40          // halves per smem row (32 data + 8 pad) -> conflict-free ldmatrix

// ---- static scratch (no allocation allowed) ----
__device__ int    g_cnt[NEXP];
__device__ int    g_list[NEXP * CAP];
__device__ int    g_slot[NTOK * 2];
__device__ float  g_cw[NTOK * 2];
__device__ __half g_xh[(size_t)NTOK * DIM];            // fp16 x
__device__ __half g_w1h[(size_t)NEXP * HIDDEN * DIM];  // fp16 weights
__device__ __half g_w3h[(size_t)NEXP * HIDDEN * DIM];
__device__ __half g_w2h[(size_t)NEXP * DIM * HIDDEN];
__device__ __half g_h[(size_t)NEXP * CAP * HIDDEN];    // compacted SwiGLU output, fp16
__device__ float  g_y[(size_t)NEXP * CAP * DIM];       // compacted GEMM2 output, fp32

// ------------------------------------------------------------------
// helpers
// ------------------------------------------------------------------
__device__ __forceinline__ uint32_t s2u(const void* p) {
    uint32_t a;
    asm("{ .reg .u64 t; cvta.to.shared.u64 t, %1; cvt.u32.u64 %0, t; }" : "=r"(a) : "l"(p));
    return a;
}
__device__ __forceinline__ void ldm4(uint32_t (&r)[4], uint32_t addr) {
    asm volatile("ldmatrix.sync.aligned.m8n8.x4.shared.b16 {%0,%1,%2,%3}, [%4];"
                 : "=r"(r[0]), "=r"(r[1]), "=r"(r[2]), "=r"(r[3]) : "r"(addr));
}
__device__ __forceinline__ void mma16816(float (&d)[4], const uint32_t (&a)[4],
                                         uint32_t b0, uint32_t b1) {
    asm volatile("mma.sync.aligned.m16n8k16.row.col.f32.f16.f16.f32 "
                 "{%0,%1,%2,%3}, {%4,%5,%6,%7}, {%8,%9}, {%0,%1,%2,%3};"
                 : "+f"(d[0]), "+f"(d[1]), "+f"(d[2]), "+f"(d[3])
                 : "r"(a[0]), "r"(a[1]), "r"(a[2]), "r"(a[3]), "r"(b0), "r"(b1));
}
__device__ __forceinline__ uint2 f4h(float4 v) {
    __half2 lo = __floats2half2_rn(v.x, v.y);
    __half2 hi = __floats2half2_rn(v.z, v.w);
    uint2 r;
    r.x = *reinterpret_cast<uint32_t*>(&lo);
    r.y = *reinterpret_cast<uint32_t*>(&hi);
    return r;
}
__device__ __forceinline__ void cp16(uint32_t dst, const void* src, uint32_t ssz) {
    asm volatile("cp.async.cg.shared.global [%0], [%1], 16, %2;"
                 :: "r"(dst), "l"(src), "r"(ssz) : "memory");
}
#define CPCOMMIT() asm volatile("cp.async.commit_group;" ::: "memory")
#define CPWAIT(n)  asm volatile("cp.async.wait_group %0;" :: "n"(n) : "memory")

// ---------------- init / convert / gating ----------------
__global__ void k_init() {
    if (threadIdx.x < NEXP) g_cnt[threadIdx.x] = 0;
}

__global__ void __launch_bounds__(256) k_cvt(const float* __restrict__ src,
                                             __half* __restrict__ dst, int n4) {
    int i = blockIdx.x * blockDim.x + threadIdx.x;
    if (i < n4) {
        float4 v = *(const float4*)(src + (size_t)i * 4);
        *(uint2*)(dst + (size_t)i * 4) = f4h(v);
    }
}

__global__ void __launch_bounds__(256) k_gate(const float* __restrict__ x,
                                              const float* __restrict__ gw) {
    int warp = (blockIdx.x * blockDim.x + threadIdx.x) >> 5;
    int lane = threadIdx.x & 31;
    if (warp >= NTOK) return;
    const float* xr = x + (size_t)warp * DIM;

    float acc[NEXP] = {0.f, 0.f, 0.f, 0.f};
    for (int i = lane; i < DIM; i += 32) {
        float xv = xr[i];
#pragma unroll
        for (int e = 0; e < NEXP; e++) acc[e] += xv * gw[e * DIM + i];
    }
#pragma unroll
    for (int o = 16; o > 0; o >>= 1) {
#pragma unroll
        for (int e = 0; e < NEXP; e++)
            acc[e] += __shfl_xor_sync(0xffffffffu, acc[e], o);
    }
    if (lane == 0) {
        float m = acc[0];
#pragma unroll
        for (int e = 1; e < NEXP; e++) m = fmaxf(m, acc[e]);
        float p[NEXP], s = 0.f;
#pragma unroll
        for (int e = 0; e < NEXP; e++) { p[e] = expf(acc[e] - m); s += p[e]; }
        float inv_s = 1.f / s;
#pragma unroll
        for (int e = 0; e < NEXP; e++) p[e] *= inv_s;

        int i0 = 0;
#pragma unroll
        for (int e = 1; e < NEXP; e++) if (p[e] > p[i0]) i0 = e;
        int i1 = -1;
#pragma unroll
        for (int e = 0; e < NEXP; e++)
            if (e != i0 && (i1 < 0 || p[e] > p[i1])) i1 = e;

        float w0 = p[i0], w1 = p[i1];
        float inv = 1.f / (w0 + w1);
        w0 *= inv; w1 *= inv;

        int q0 = atomicAdd(&g_cnt[i0], 1);
        g_list[i0 * CAP + q0] = warp;
        g_slot[warp * 2 + 0] = i0 * CAP + q0;
        g_cw[warp * 2 + 0] = w0;
        int q1 = atomicAdd(&g_cnt[i1], 1);
        g_list[i1 * CAP + q1] = warp;
        g_slot[warp * 2 + 1] = i1 * CAP + q1;
        g_cw[warp * 2 + 1] = w1;
    }
}

// ------------------------------------------------------------------
// GEMM1: g_h = fp16( silu(Xg W1^T) * (Xg W3^T) ), cp.async 3-stage
// grid (HIDDEN/128=20, CAP/TM=64, NEXP), block 256.
// 8 warps: warps 0-3 compute acc1 (W1) quadrants 64x64, warps 4-7 acc3 (W3).
// Epilogue: acc3 warps park frags in smem; acc1 warps fuse silu*mul.
// ------------------------------------------------------------------
#define G1_MAT_B   (128 * PAD * 2)          // 10240 B per matrix
#define G1_STAGE_B (3 * G1_MAT_B)           // 30720 B per stage
#define G1_S       3
#define G1_SMEM    (G1_S * G1_STAGE_B)      // 92160 B

__global__ void __launch_bounds__(256) k_ffn1() {
    int e  = blockIdx.z;
    int m0 = blockIdx.y * TM;
    int h0 = blockIdx.x * 128;
    int cnt = g_cnt[e];
    if (m0 >= cnt) return;

    extern __shared__ __half sm[];
    __shared__ int rows_sh[TM];

    int tid = threadIdx.x;
    int wid = tid >> 5;
    int lane = tid & 31;
    if (tid < TM) {
        int m = m0 + tid;
        rows_sh[tid] = (m < cnt) ? g_list[e * CAP + m] : -1;
    }
    __syncthreads();

    // loader mapping (identical to prior passing kernel)
    const __half* pA[2]; const __half* pW1[2]; const __half* pW3[2];
    uint32_t soff[2], asz[2];
#pragma unroll
    for (int q = 0; q < 2; q++) {
        int idx = tid + q * 256;
        int row = idx >> 2;
        int c   = idx & 3;
        soff[q] = (row * PAD + c * 8) * 2;
        int tok = rows_sh[row];
        asz[q] = (tok >= 0) ? 16u : 0u;
        pA[q]  = g_xh + ((tok >= 0) ? ((size_t)tok * DIM) : 0) + c * 8;
        pW1[q] = g_w1h + ((size_t)e * HIDDEN + h0 + row) * DIM + c * 8;
        pW3[q] = g_w3h + ((size_t)e * HIDDEN + h0 + row) * DIM + c * 8;
    }

    // warp role: matsel 0 -> W1/acc1, 1 -> W3/acc3; quadrant q = wid&3
    int matsel = wid >> 2;
    int quad = wid & 3;
    int wm = (quad >> 1) * 64;
    int wn = (quad & 1) * 64;

    float acc[4][8][4];
#pragma unroll
    for (int i = 0; i < 4; i++)
#pragma unroll
        for (int j = 0; j < 8; j++)
#pragma unroll
            for (int f = 0; f < 4; f++) acc[i][j][f] = 0.f;

    uint32_t smb = s2u(sm);

    auto LOAD = [&](int buf, int k) {
        uint32_t st = smb + buf * G1_STAGE_B;
        int ko = k * BK;
#pragma unroll
        for (int q = 0; q < 2; q++) {
            cp16(st + soff[q],              pA[q]  + ko, asz[q]);
            cp16(st + G1_MAT_B + soff[q],   pW1[q] + ko, 16u);
            cp16(st + 2*G1_MAT_B + soff[q], pW3[q] + ko, 16u);
        }
    };
    auto COMPUTE = [&](int buf) {
        uint32_t sb = smb + buf * G1_STAGE_B;
        uint32_t matB = sb + (matsel ? 2 * G1_MAT_B : G1_MAT_B);
        uint32_t aAddr = sb + ((wm + (lane & 15)) * PAD + (lane >> 4) * 8) * 2;
        uint32_t bBase = ((wn + ((lane >> 4) << 3) + (lane & 7)) * PAD + ((lane >> 3) & 1) * 8) * 2;
#pragma unroll
        for (int ks = 0; ks < 2; ks++) {
            uint32_t a[4][4];
#pragma unroll
            for (int mt = 0; mt < 4; mt++)
                ldm4(a[mt], aAddr + (mt * 16 * PAD + ks * 16) * 2);
#pragma unroll
            for (int nf = 0; nf < 4; nf++) {
                uint32_t b[4];
                ldm4(b, matB + bBase + (nf * 16 * PAD + ks * 16) * 2);
#pragma unroll
                for (int mt = 0; mt < 4; mt++) {
                    mma16816(acc[mt][2 * nf + 0], a[mt], b[0], b[1]);
                    mma16816(acc[mt][2 * nf + 1], a[mt], b[2], b[3]);
                }
            }
        }
    };

    const int nK = DIM / BK;   // 32
#pragma unroll
    for (int s = 0; s < G1_S - 1; s++) { LOAD(s, s); CPCOMMIT(); }
    for (int k = 0; k < nK; k++) {
        CPWAIT(G1_S - 2);
        __syncthreads();
        COMPUTE(k % G1_S);
        int kn = k + G1_S - 1;
        if (kn < nK) LOAD(kn % G1_S, kn);
        CPCOMMIT();
    }
    CPWAIT(0);
    __syncthreads();   // pipeline smem now free for exchange

    // exchange: acc3 warps write frags (idx-major, conflict-free)
    float* xch = (float*)sm;   // 4 regions x 16KB = 64KB <= 92KB
    if (matsel == 1) {
        float* dst = xch + quad * 4096;
        int idx = 0;
#pragma unroll
        for (int mt = 0; mt < 4; mt++)
#pragma unroll
            for (int nt = 0; nt < 8; nt++)
#pragma unroll
                for (int f = 0; f < 4; f++)
                    dst[(idx++) * 32 + lane] = acc[mt][nt][f];
    }
    __syncthreads();

    // acc1 warps: silu(acc1) * acc3 -> g_h (fp16, compacted)
    if (matsel == 0) {
        const float* src = xch + quad * 4096;
#pragma unroll
        for (int mt = 0; mt < 4; mt++) {
#pragma unroll
            for (int nt = 0; nt < 8; nt++) {
                int c = h0 + wn + nt * 8 + 2 * (lane & 3);
#pragma unroll
                for (int hpart = 0; hpart < 2; hpart++) {
                    int r = wm + mt * 16 + (lane >> 2) + hpart * 8;
                    if (m0 + r < cnt) {
                        int base = (mt * 8 + nt) * 4 + hpart * 2;
                        float A0 = acc[mt][nt][hpart * 2 + 0];
                        float A1 = acc[mt][nt][hpart * 2 + 1];
                        float B0 = src[(base + 0) * 32 + lane];
                        float B1 = src[(base + 1) * 32 + lane];
                        float s0 = (A0 / (1.f + expf(-A0))) * B0;
                        float s1 = (A1 / (1.f + expf(-A1))) * B1;
                        *(__half2*)&g_h[((size_t)e * CAP + m0 + r) * HIDDEN + c] =
                            __floats2half2_rn(s0, s1);
                    }
                }
            }
        }
    }
}

// ------------------------------------------------------------------
// GEMM2: g_y = h W2^T  (compacted rows), cp.async 3-stage
// grid (DIM/256=4, CAP/TM=64, NEXP), block 256.
// Block tile 128x256, 8 warps as 2x4 of 64x64.
// ------------------------------------------------------------------
#define G2_A_B     (128 * PAD * 2)          // 10240 B
#define G2_B_B     (256 * PAD * 2)          // 20480 B
#define G2_STAGE_B (G2_A_B + G2_B_B)        // 30720 B
#define G2_S       3
#define G2_SMEM    (G2_S * G2_STAGE_B)      // 92160 B

__global__ void __launch_bounds__(256) k_ffn2() {
    int e  = blockIdx.z;
    int m0 = blockIdx.y * TM;
    int d0 = blockIdx.x * 256;
    int cnt = g_cnt[e];
    if (m0 >= cnt) return;

    extern __shared__ __half sm[];

    int tid = threadIdx.x;
    int wid = tid >> 5;
    int lane = tid & 31;

    // A loader: 128 rows x 4 chunks = 512 slots (q<2)
    const __half* pA[2]; uint32_t aoff[2], asz[2];
#pragma unroll
    for (int q = 0; q < 2; q++) {
        int idx = tid + q * 256;
        int row = idx >> 2;
        int c   = idx & 3;
        aoff[q] = (row * PAD + c * 8) * 2;
        bool ok = (m0 + row) < cnt;
        asz[q] = ok ? 16u : 0u;
        pA[q] = g_h + ((size_t)e * CAP + m0 + (ok ? row : 0)) * HIDDEN + c * 8;
    }
    // B loader: 256 rows x 4 chunks = 1024 slots (q<4)
    const __half* pB[4]; uint32_t boff[4];
#pragma unroll
    for (int q = 0; q < 4; q++) {
        int idx = tid + q * 256;
        int row = idx >> 2;
        int c   = idx & 3;
        boff[q] = (row * PAD + c * 8) * 2;
        pB[q] = g_w2h + ((size_t)e * DIM + d0 + row) * HIDDEN + c * 8;
    }

    float acc[4][8][4];
#pragma unroll
    for (int i = 0; i < 4; i++)
#pragma unroll
        for (int j = 0; j < 8; j++)
#pragma unroll
            for (int f = 0; f < 4; f++) acc[i][j][f] = 0.f;

    int wm = (wid >> 2) * 64;
    int wn = (wid & 3) * 64;
    uint32_t smb = s2u(sm);

    auto LOAD = [&](int buf, int k) {
        uint32_t st = smb + buf * G2_STAGE_B;
        int ko = k * BK;
#pragma unroll
        for (int q = 0; q < 2; q++)
            cp16(st + aoff[q], pA[q] + ko, asz[q]);
#pragma unroll
        for (int q = 0; q < 4; q++)
            cp16(st + G2_A_B + boff[q], pB[q] + ko, 16u);
    };
    auto COMPUTE = [&](int buf) {
        uint32_t sb = smb + buf * G2_STAGE_B;
        uint32_t matB = sb + G2_A_B;
        uint32_t aAddr = sb + ((wm + (lane & 15)) * PAD + (lane >> 4) * 8) * 2;
        uint32_t bBase = ((wn + ((lane >> 4) << 3) + (lane & 7)) * PAD + ((lane >> 3) & 1) * 8) * 2;
#pragma unroll
        for (int ks = 0; ks < 2; ks++) {
            uint32_t a[4][4];
#pragma unroll
            for (int mt = 0; mt < 4; mt++)
                ldm4(a[mt], aAddr + (mt * 16 * PAD + ks * 16) * 2);
#pragma unroll
            for (int nf = 0; nf < 4; nf++) {
                uint32_t b[4];
                ldm4(b, matB + bBase + (nf * 16 * PAD + ks * 16) * 2);
#pragma unroll
                for (int mt = 0; mt < 4; mt++) {
                    mma16816(acc[mt][2 * nf + 0], a[mt], b[0], b[1]);
                    mma16816(acc[mt][2 * nf + 1], a[mt], b[2], b[3]);
                }
            }
        }
    };

    const int nK = HIDDEN / BK;   // 80
#pragma unroll
    for (int s = 0; s < G2_S - 1; s++) { LOAD(s, s); CPCOMMIT(); }
    for (int k = 0; k < nK; k++) {
        CPWAIT(G2_S - 2);
        __syncthreads();
        COMPUTE(k % G2_S);
        int kn = k + G2_S - 1;
        if (kn < nK) LOAD(kn % G2_S, kn);
        CPCOMMIT();
    }

    // epilogue: plain store to compacted y scratch
#pragma unroll
    for (int mt = 0; mt < 4; mt++) {
#pragma unroll
        for (int nt = 0; nt < 8; nt++) {
            int c = d0 + wn + nt * 8 + 2 * (lane & 3);
#pragma unroll
            for (int hpart = 0; hpart < 2; hpart++) {
                int r = wm + mt * 16 + (lane >> 2) + hpart * 8;
                if (m0 + r < cnt) {
                    float2 v = make_float2(acc[mt][nt][hpart * 2 + 0],
                                           acc[mt][nt][hpart * 2 + 1]);
                    *(float2*)&g_y[((size_t)e * CAP + m0 + r) * DIM + c] = v;
                }
            }
        }
    }
}

// ---------------- combine: out[t] = w0*y[s0] + w1*y[s1] ----------------
__global__ void __launch_bounds__(256) k_comb(float* __restrict__ out) {
    int t = blockIdx.x;
    int d = threadIdx.x * 4;
    int s0 = g_slot[t * 2 + 0], s1 = g_slot[t * 2 + 1];
    float w0 = g_cw[t * 2 + 0], w1 = g_cw[t * 2 + 1];
    float4 y0 = *(const float4*)&g_y[(size_t)s0 * DIM + d];
    float4 y1 = *(const float4*)&g_y[(size_t)s1 * DIM + d];
    float4 o;
    o.x = w0 * y0.x + w1 * y1.x;
    o.y = w0 * y0.y + w1 * y1.y;
    o.z = w0 * y0.z + w1 * y1.z;
    o.w = w0 * y0.w + w1 * y1.w;
    *(float4*)&out[(size_t)t * DIM + d] = o;
}

// ---------------- launch ----------------
extern "C" void kernel_launch(void* const* d_in, const int* in_sizes, int n_in,
                              void* d_out, int out_size) {
    const float* x  = (const float*)d_in[0];
    const float* gw = (const float*)d_in[1];
    const float* w1 = (const float*)d_in[2];
    const float* w2 = (const float*)d_in[3];
    const float* w3 = (const float*)d_in[4];
    float* out = (float*)d_out;

    static int configured = 0;
    if (!configured) {
        cudaFuncSetAttribute(k_ffn1, cudaFuncAttributeMaxDynamicSharedMemorySize, G1_SMEM);
        cudaFuncSetAttribute(k_ffn2, cudaFuncAttributeMaxDynamicSharedMemorySize, G2_SMEM);
        configured = 1;
    }

    cudaMemsetAsync(out, 0, (size_t)out_size * sizeof(float), 0);

    k_init<<<1, 32>>>();

    // fp32 -> fp16 conversions (x + all weights)
    {
        __half* dxh;  cudaGetSymbolAddress((void**)&dxh,  g_xh);
        __half* dw1h; cudaGetSymbolAddress((void**)&dw1h, g_w1h);
        __half* dw3h; cudaGetSymbolAddress((void**)&dw3h, g_w3h);
        __half* dw2h; cudaGetSymbolAddress((void**)&dw2h, g_w2h);
        int nx = NTOK * DIM / 4;
        int nw = NEXP * HIDDEN * DIM / 4;
        k_cvt<<<(nx + 255) / 256, 256>>>(x,  dxh,  nx);
        k_cvt<<<(nw + 255) / 256, 256>>>(w1, dw1h, nw);
        k_cvt<<<(nw + 255) / 256, 256>>>(w3, dw3h, nw);
        k_cvt<<<(nw + 255) / 256, 256>>>(w2, dw2h, nw);
    }

    k_gate<<<(NTOK * 32) / 256, 256>>>(x, gw);

    dim3 g1(HIDDEN / 128, CAP / TM, NEXP);
    k_ffn1<<<g1, 256, G1_SMEM>>>();

    dim3 g2(DIM / 256, CAP / TM, NEXP);
    k_ffn2<<<g2, 256, G2_SMEM>>>();

    k_comb<<<NTOK, 256>>>(out);
}